// round 4
// baseline (speedup 1.0000x reference)
#include <cuda_runtime.h>
#include <cuda_bf16.h>

// Problem constants
#define B_ROWS   65536
#define FDIM     512
#define WARPS_PER_BLOCK 8
#define THREADS_PER_BLOCK (WARPS_PER_BLOCK * 32)
#define NUM_BLOCKS (B_ROWS / WARPS_PER_BLOCK)   // 8192

// Deterministic reduction scratch (no allocation allowed)
__device__ float g_partial[NUM_BLOCKS];
__device__ unsigned int g_count;   // zero-init; last block resets to 0 each replay

__global__ __launch_bounds__(THREADS_PER_BLOCK)
void predict_kernel(const float* __restrict__ input,
                    const float* __restrict__ factor,
                    const int* __restrict__ label,     // int32 (JAX x64 disabled)
                    const float* __restrict__ centers,
                    float* __restrict__ out,           // out[0]=loss, out[1..B]=predict_a
                    int out_size)
{
    __shared__ float s_loss[WARPS_PER_BLOCK];
    __shared__ bool  s_is_last;

    const int warp_in_block = threadIdx.x >> 5;
    const int lane = threadIdx.x & 31;
    const int row = blockIdx.x * WARPS_PER_BLOCK + warp_in_block;

    const int lab = label[row];

    const float4* __restrict__ in4 = reinterpret_cast<const float4*>(input + (size_t)row * FDIM);
    const float4* __restrict__ c4  = reinterpret_cast<const float4*>(centers + (size_t)lab * FDIM);

    // ---- Front-batched loads: 8 independent LDG.128 in flight per thread ----
    float4 a[4], c[4];
#pragma unroll
    for (int i = 0; i < 4; i++)
        a[i] = __ldcs(&in4[lane + i * 32]);   // streaming: read-once
#pragma unroll
    for (int i = 0; i < 4; i++)
        c[i] = __ldg(&c4[lane + i * 32]);     // cached: 2.66 MB reused set

    // ---- 4 independent accumulator chains ----
    float acc0 = 0.f, acc1 = 0.f, acc2 = 0.f, acc3 = 0.f;
#pragma unroll
    for (int i = 0; i < 4; i++) {
        acc0 = fmaf(a[i].x, c[i].x, acc0);
        acc1 = fmaf(a[i].y, c[i].y, acc1);
        acc2 = fmaf(a[i].z, c[i].z, acc2);
        acc3 = fmaf(a[i].w, c[i].w, acc3);
    }
    float acc = (acc0 + acc1) + (acc2 + acc3);

    // warp reduce
#pragma unroll
    for (int off = 16; off > 0; off >>= 1)
        acc += __shfl_xor_sync(0xFFFFFFFFu, acc, off);

    if (lane == 0) {
        float p = 12.0f * tanhf(acc);
        if (1 + row < out_size) out[1 + row] = p;
        float d = p - factor[row];
        float ad = fabsf(d);
        float l = (ad < 1.0f) ? 0.5f * d * d : (ad - 0.5f);
        s_loss[warp_in_block] = l;
    }
    __syncthreads();

    if (threadIdx.x == 0) {
        float s = 0.0f;
#pragma unroll
        for (int w = 0; w < WARPS_PER_BLOCK; w++) s += s_loss[w];
        g_partial[blockIdx.x] = s;
        __threadfence();
        unsigned int old = atomicAdd(&g_count, 1u);
        s_is_last = (old == NUM_BLOCKS - 1);
    }
    __syncthreads();

    // Last-arriving block reduces all partials in a FIXED order (deterministic).
    if (s_is_last) {
        __shared__ float s_red[THREADS_PER_BLOCK];
        float accr = 0.0f;
#pragma unroll
        for (int i = 0; i < NUM_BLOCKS / THREADS_PER_BLOCK; i++)   // 32 each
            accr += g_partial[threadIdx.x + i * THREADS_PER_BLOCK];
        s_red[threadIdx.x] = accr;
        __syncthreads();
#pragma unroll
        for (int stride = THREADS_PER_BLOCK / 2; stride > 0; stride >>= 1) {
            if (threadIdx.x < stride) s_red[threadIdx.x] += s_red[threadIdx.x + stride];
            __syncthreads();
        }
        if (threadIdx.x == 0) {
            out[0] = s_red[0] * (1.0f / (float)B_ROWS);
            __threadfence();
            g_count = 0;   // reset for next graph replay
        }
    }
}

extern "C" void kernel_launch(void* const* d_in, const int* in_sizes, int n_in,
                              void* d_out, int out_size)
{
    const float* input   = (const float*)d_in[0];
    const float* factor  = (const float*)d_in[1];
    const int*   label   = (const int*)d_in[2];
    const float* centers = (const float*)d_in[3];
    float* out = (float*)d_out;

    predict_kernel<<<NUM_BLOCKS, THREADS_PER_BLOCK>>>(input, factor, label, centers, out, out_size);
}

// round 6
// speedup vs baseline: 1.2568x; 1.2568x over previous
#include <cuda_runtime.h>
#include <cuda_bf16.h>

// Problem constants
#define B_ROWS   65536
#define FDIM     512
#define WARPS_PER_BLOCK 8
#define THREADS_PER_BLOCK (WARPS_PER_BLOCK * 32)
#define NUM_BLOCKS (148 * 8)                       // persistent: one wave, 8 blocks/SM
#define TOTAL_WARPS (NUM_BLOCKS * WARPS_PER_BLOCK) // 9472

// Deterministic reduction scratch (no allocation allowed)
__device__ float g_partial[NUM_BLOCKS];
__device__ unsigned int g_count;   // zero-init; last block resets to 0 each replay

__global__ __launch_bounds__(THREADS_PER_BLOCK)
void predict_kernel(const float* __restrict__ input,
                    const float* __restrict__ factor,
                    const int* __restrict__ label,     // int32 (JAX x64 disabled)
                    const float* __restrict__ centers,
                    float* __restrict__ out,           // out[0]=loss, out[1..B]=predict_a
                    int out_size)
{
    __shared__ float s_loss[WARPS_PER_BLOCK];
    __shared__ bool  s_is_last;

    const int warp_in_block = threadIdx.x >> 5;
    const int lane = threadIdx.x & 31;
    const int gwarp = blockIdx.x * WARPS_PER_BLOCK + warp_in_block;

    float warp_loss = 0.0f;   // lane 0 accumulates, fixed stride order -> deterministic

    // Grid-stride over rows: ~7 rows per warp, no barriers inside the loop.
    for (int row = gwarp; row < B_ROWS; row += TOTAL_WARPS) {
        const int lab = label[row];

        const float4* __restrict__ in4 = reinterpret_cast<const float4*>(input + (size_t)row * FDIM);
        const float4* __restrict__ c4  = reinterpret_cast<const float4*>(centers + (size_t)lab * FDIM);

        float acc = 0.0f;
#pragma unroll
        for (int i = 0; i < FDIM / (32 * 4); i++) {   // 4 iterations, interleaved (R3 pattern)
            float4 a = __ldcs(&in4[lane + i * 32]);   // streaming: read-once
            float4 c = __ldg(&c4[lane + i * 32]);     // cached: 2.66 MB reused set
            acc = fmaf(a.x, c.x, acc);
            acc = fmaf(a.y, c.y, acc);
            acc = fmaf(a.z, c.z, acc);
            acc = fmaf(a.w, c.w, acc);
        }

        // warp reduce
#pragma unroll
        for (int off = 16; off > 0; off >>= 1)
            acc += __shfl_xor_sync(0xFFFFFFFFu, acc, off);

        if (lane == 0) {
            float p = 12.0f * tanhf(acc);
            if (1 + row < out_size) out[1 + row] = p;
            float d = p - factor[row];
            float ad = fabsf(d);
            warp_loss += (ad < 1.0f) ? 0.5f * d * d : (ad - 0.5f);
        }
    }

    if (lane == 0) s_loss[warp_in_block] = warp_loss;
    __syncthreads();

    if (threadIdx.x == 0) {
        float s = 0.0f;
#pragma unroll
        for (int w = 0; w < WARPS_PER_BLOCK; w++) s += s_loss[w];
        g_partial[blockIdx.x] = s;
        __threadfence();
        unsigned int old = atomicAdd(&g_count, 1u);
        s_is_last = (old == NUM_BLOCKS - 1);
    }
    __syncthreads();

    // Last-arriving block reduces all partials in a FIXED order (deterministic).
    if (s_is_last) {
        __shared__ float s_red[THREADS_PER_BLOCK];
        float accr = 0.0f;
        for (int i = threadIdx.x; i < NUM_BLOCKS; i += THREADS_PER_BLOCK)
            accr += g_partial[i];
        s_red[threadIdx.x] = accr;
        __syncthreads();
#pragma unroll
        for (int stride = THREADS_PER_BLOCK / 2; stride > 0; stride >>= 1) {
            if (threadIdx.x < stride) s_red[threadIdx.x] += s_red[threadIdx.x + stride];
            __syncthreads();
        }
        if (threadIdx.x == 0) {
            out[0] = s_red[0] * (1.0f / (float)B_ROWS);
            __threadfence();
            g_count = 0;   // reset for next graph replay
        }
    }
}

extern "C" void kernel_launch(void* const* d_in, const int* in_sizes, int n_in,
                              void* d_out, int out_size)
{
    const float* input   = (const float*)d_in[0];
    const float* factor  = (const float*)d_in[1];
    const int*   label   = (const int*)d_in[2];
    const float* centers = (const float*)d_in[3];
    float* out = (float*)d_out;

    predict_kernel<<<NUM_BLOCKS, THREADS_PER_BLOCK>>>(input, factor, label, centers, out, out_size);
}